// round 3
// baseline (speedup 1.0000x reference)
#include <cuda_runtime.h>
#include <math.h>

#define BB 16
#define GG 4
#define CGc 64
#define HH 64
#define WW 64
#define HWs 4096
#define KK 9

// scratch (static __device__ arrays; no allocation)
__device__ float g_off[BB*GG*18*HWs];        // predicted offsets [b][g][c=2k+j][h][w]
__device__ float g_wt2[GG*KK*CGc*128];       // def_w transposed+duplicated: [g][k][ic][2*oc+{0,1}]
__device__ float g_owt[GG*CGc*KK*20];        // off_w transposed: [g][ic][tap][c pad 20]

// ---- packed f32x2 helpers (FFMA2 path; ptxas never auto-generates these) ----
__device__ __forceinline__ unsigned long long fma2(unsigned long long a,
                                                   unsigned long long b,
                                                   unsigned long long c) {
    unsigned long long d;
    asm("fma.rn.f32x2 %0, %1, %2, %3;" : "=l"(d) : "l"(a), "l"(b), "l"(c));
    return d;
}
__device__ __forceinline__ unsigned long long pack2(float v) {
    unsigned long long d;
    asm("mov.b64 %0, {%1, %1};" : "=l"(d) : "f"(v));
    return d;
}
__device__ __forceinline__ float2 unpack2(unsigned long long v) {
    float2 r;
    asm("mov.b64 {%0, %1}, %2;" : "=f"(r.x), "=f"(r.y) : "l"(v));
    return r;
}

// ---------------- prep: weight transposes ----------------
__global__ void prep_kernel(const float* __restrict__ off_w,
                            const float* __restrict__ def_w) {
    int idx = blockIdx.x * blockDim.x + threadIdx.x;
    const int n2 = GG*KK*CGc*128;     // 294912  duplicated deform weights
    if (idx < n2) {
        int oc = (idx & 127) >> 1;
        int ic = (idx >> 7) & 63;
        int gk = idx >> 13;           // g*9+k
        int k  = gk % KK;
        int g  = gk / KK;
        g_wt2[idx] = def_w[((g*CGc + oc)*CGc + ic)*KK + k];
    }
    const int n_owt = GG*CGc*KK*20;   // 46080
    if (idx < n_owt) {
        int c  = idx % 20;
        int t  = (idx / 20) % KK;
        int ic = (idx / 180) % CGc;
        int g  = idx / (180*CGc);
        g_owt[idx] = (c < 18) ? off_w[((g*18 + c)*CGc + ic)*KK + t] : 0.0f;
    }
}

// ---------------- offset conv: 64 -> 18, 3x3 ----------------
// block = (b,g,h); 256 threads = 64 w * 4 ic-chunks; f32x2 packed channels
extern __shared__ float smem1[];
__global__ void __launch_bounds__(256) offset_kernel(const float* __restrict__ x,
                                                     const float* __restrict__ off_b) {
    float* sx = smem1;              // 3*64*64 = 12288 floats (x tile, rows h-1..h+1)
    float* sw = smem1 + 12288;      // 64*9*20 = 11520 floats (transposed weights)

    int bid = blockIdx.x;
    int h = bid & 63;
    int g = (bid >> 6) & 3;
    int b = bid >> 8;
    int tid = threadIdx.x;

    const float* owt = g_owt + g*CGc*KK*20;
    for (int i = tid; i < CGc*KK*20; i += 256) sw[i] = owt[i];

    const float* xb = x + (size_t)(b*GG + g) * CGc * HWs;
    for (int i = tid; i < 3*CGc*WW; i += 256) {
        int ky = i >> 12;
        int ic = (i >> 6) & 63;
        int w  = i & 63;
        int row = h - 1 + ky;
        sx[i] = (row >= 0 && row < HH) ? xb[ic*HWs + row*WW + w] : 0.0f;
    }
    __syncthreads();

    int w   = tid & 63;
    int sub = tid >> 6;   // ic chunk 0..3

    unsigned long long acc2[9];   // 18 channels as 9 f32x2 packs
#pragma unroll
    for (int p = 0; p < 9; p++) acc2[p] = 0ULL;

#pragma unroll
    for (int ky = 0; ky < 3; ky++) {
        const float* sxk = sx + ky*4096;
        for (int ic = sub*16; ic < sub*16 + 16; ic++) {
            const float* xr = sxk + ic*64;
            float xv0 = (w > 0)  ? xr[w-1] : 0.0f;   // kx=0 -> col w-1
            float xv1 = xr[w];                        // kx=1
            float xv2 = (w < 63) ? xr[w+1] : 0.0f;   // kx=2
            const ulonglong2* wp = (const ulonglong2*)(sw + (ic*KK + ky*3)*20);
#pragma unroll
            for (int kx = 0; kx < 3; kx++) {
                float xs = (kx == 0) ? xv0 : ((kx == 1) ? xv1 : xv2);
                unsigned long long xp = pack2(xs);
#pragma unroll
                for (int q = 0; q < 4; q++) {
                    ulonglong2 wv = wp[kx*5 + q];         // channels 4q..4q+3
                    acc2[2*q]   = fma2(wv.x, xp, acc2[2*q]);
                    acc2[2*q+1] = fma2(wv.y, xp, acc2[2*q+1]);
                }
                {   // q=4 -> channels 16,17 only
                    ulonglong2 wv = wp[kx*5 + 4];
                    acc2[8] = fma2(wv.x, xp, acc2[8]);
                }
            }
        }
    }
    __syncthreads();

    // partial-sum reduction via smem (reuse sx region): red[sub][c][w]
    float* red = sx;
#pragma unroll
    for (int p = 0; p < 9; p++) {
        float2 v = unpack2(acc2[p]);
        red[(sub*18 + 2*p    )*64 + w] = v.x;
        red[(sub*18 + 2*p + 1)*64 + w] = v.y;
    }
    __syncthreads();

    for (int i = tid; i < 18*64; i += 256) {
        int c = i >> 6, ww = i & 63;
        float s = red[(0*18 + c)*64 + ww] + red[(1*18 + c)*64 + ww]
                + red[(2*18 + c)*64 + ww] + red[(3*18 + c)*64 + ww]
                + off_b[g*18 + c];
        g_off[((size_t)(b*GG + g)*18 + c)*HWs + h*64 + ww] = s;
    }
}

// ---------------- deformable conv main kernel ----------------
// block = (b,g,h); 128 threads; per-tap: gather S[ic][w], f32x2 GEMM 64oc x 64w x 64ic
extern __shared__ float smem2[];
__global__ void __launch_bounds__(128) deform_kernel(const float* __restrict__ x,
                                                     const float* __restrict__ def_b,
                                                     float* __restrict__ out) {
    float*  S   = smem2;                          // 4096 floats
    float*  Wt2 = smem2 + 4096;                   // 8192 floats  [ic][2*oc+{0,1}] dup pairs
    float4* cw  = (float4*)(smem2 + 12288);       // 576 float4: masked bilinear weights
    int4*   co  = (int4*)  (smem2 + 12288 + 2304);// 576 int4: clamped corner offsets

    int bid = blockIdx.x;
    int h = bid & 63;
    int g = (bid >> 6) & 3;
    int b = bid >> 8;
    int tid = threadIdx.x;

    const float* xb = x + (size_t)(b*GG + g) * CGc * HWs;

    // precompute per-(tap,w) corner offsets + masked weights
    const float* offp = g_off + (size_t)(b*GG + g)*18*HWs + h*64;
    for (int i = tid; i < KK*64; i += 128) {
        int k = i >> 6, ww = i & 63;
        float dy = offp[(2*k    )*HWs + ww];
        float dx = offp[(2*k + 1)*HWs + ww];
        float py = dy + (float)(k/3 - 1) + (float)h;
        float px = dx + (float)(k%3 - 1) + (float)ww;
        float fy = floorf(py), fx = floorf(px);
        float wy = py - fy,    wx = px - fx;
        int y0 = (int)fy, x0 = (int)fx;
        int y1 = y0 + 1,  x1 = x0 + 1;
        float vy0 = (y0 >= 0 && y0 < HH) ? 1.f : 0.f;
        float vy1 = (y1 >= 0 && y1 < HH) ? 1.f : 0.f;
        float vx0 = (x0 >= 0 && x0 < WW) ? 1.f : 0.f;
        float vx1 = (x1 >= 0 && x1 < WW) ? 1.f : 0.f;
        float w00 = (1.f-wy)*(1.f-wx) * vy0 * vx0;
        float w01 = (1.f-wy)*wx       * vy0 * vx1;
        float w10 = wy*(1.f-wx)       * vy1 * vx0;
        float w11 = wy*wx             * vy1 * vx1;
        int y0c = min(max(y0,0),HH-1), y1c = min(max(y1,0),HH-1);
        int x0c = min(max(x0,0),WW-1), x1c = min(max(x1,0),WW-1);
        cw[i] = make_float4(w00, w01, w10, w11);
        co[i] = make_int4(y0c*WW + x0c, y0c*WW + x1c, y1c*WW + x0c, y1c*WW + x1c);
    }
    __syncthreads();

    unsigned long long acc2[8][2];   // 8 oc x (4 w as 2 f32x2 packs)
#pragma unroll
    for (int r = 0; r < 8; r++) { acc2[r][0] = 0ULL; acc2[r][1] = 0ULL; }

    int wq  = tid & 15;
    int ocq = tid >> 4;
    int w0  = wq * 4;
    int oc0 = ocq * 8;

    const float* wtg2 = g_wt2 + (size_t)g * KK * CGc * 128;

    for (int k = 0; k < KK; k++) {
        // fill Wt2[ic][2*oc] duplicated pairs (coalesced float4 copy, 32KB)
        {
            const float4* src = (const float4*)(wtg2 + k*CGc*128);
            float4* dst = (float4*)Wt2;
            for (int i = tid; i < CGc*128/4; i += 128) dst[i] = src[i];
        }
        // fill S[ic][w]: 4-corner bilinear gather
        for (int i = tid; i < CGc*64; i += 128) {
            int ic = i >> 6, ww = i & 63;
            float4 wv = cw[k*64 + ww];
            int4   ov = co[k*64 + ww];
            const float* p = xb + ic*HWs;
            S[i] = wv.x * __ldg(p + ov.x) + wv.y * __ldg(p + ov.y)
                 + wv.z * __ldg(p + ov.z) + wv.w * __ldg(p + ov.w);
        }
        __syncthreads();

#pragma unroll 4
        for (int ic = 0; ic < CGc; ic++) {
            ulonglong2 sv = *(const ulonglong2*)(S + ic*64 + w0);       // (w0,w0+1),(w0+2,w0+3)
            const ulonglong2* wp = (const ulonglong2*)(Wt2 + ic*128 + oc0*2);
            ulonglong2 wa = wp[0];   // (w[oc0],w[oc0]),(w[oc0+1],w[oc0+1])
            ulonglong2 wb = wp[1];
            ulonglong2 wc = wp[2];
            ulonglong2 wd = wp[3];
#define FMA2_ROW(r, wpk) \
            acc2[r][0] = fma2((wpk), sv.x, acc2[r][0]); \
            acc2[r][1] = fma2((wpk), sv.y, acc2[r][1]);
            FMA2_ROW(0, wa.x) FMA2_ROW(1, wa.y)
            FMA2_ROW(2, wb.x) FMA2_ROW(3, wb.y)
            FMA2_ROW(4, wc.x) FMA2_ROW(5, wc.y)
            FMA2_ROW(6, wd.x) FMA2_ROW(7, wd.y)
#undef FMA2_ROW
        }
        __syncthreads();
    }

    float* ob = out + (size_t)(b*GG + g)*CGc*HWs + h*64;
#pragma unroll
    for (int r = 0; r < 8; r++) {
        float bias = def_b[g*CGc + oc0 + r];
        float2 v0 = unpack2(acc2[r][0]);
        float2 v1 = unpack2(acc2[r][1]);
        float4 v = make_float4(v0.x + bias, v0.y + bias, v1.x + bias, v1.y + bias);
        *(float4*)(ob + (oc0 + r)*HWs + w0) = v;
    }
}

// ---------------- launch ----------------
extern "C" void kernel_launch(void* const* d_in, const int* in_sizes, int n_in,
                              void* d_out, int out_size) {
    const float* x     = (const float*)d_in[0];
    const float* off_w = (const float*)d_in[1];
    const float* off_b = (const float*)d_in[2];
    const float* def_w = (const float*)d_in[3];
    const float* def_b = (const float*)d_in[4];
    float* out = (float*)d_out;

    cudaFuncSetAttribute(offset_kernel, cudaFuncAttributeMaxDynamicSharedMemorySize,
                         (12288 + 11520) * (int)sizeof(float));   // 95232 B
    cudaFuncSetAttribute(deform_kernel, cudaFuncAttributeMaxDynamicSharedMemorySize,
                         16896 * (int)sizeof(float));             // 67584 B

    prep_kernel<<<(GG*KK*CGc*128 + 255) / 256, 256>>>(off_w, def_w);
    offset_kernel<<<BB*GG*HH, 256, (12288 + 11520) * sizeof(float)>>>(x, off_b);
    deform_kernel<<<BB*GG*HH, 128, 16896 * sizeof(float)>>>(x, def_b, out);
}

// round 5
// speedup vs baseline: 2.0469x; 2.0469x over previous
#include <cuda_runtime.h>
#include <cuda_bf16.h>
#include <math.h>
#include <stdint.h>

#define BB 16
#define GG 4
#define CGc 64
#define HH 64
#define WW 64
#define HWs 4096
#define KK 9

// ---------------- scratch (static; no allocation) ----------------
__device__ float g_off[BB*GG*18*HWs];                 // offsets [bg][c=2k+j][h][w]
__device__ float g_owt[GG*CGc*KK*20];                 // off_w transposed: [g][ic][tap][c pad 20]
__device__ __nv_bfloat16 g_wbh[GG*KK*CGc*CGc];        // def_w bf16 hi, pre-SW128-swizzled rows [oc][ic]
__device__ __nv_bfloat16 g_wbl[GG*KK*CGc*CGc];        // def_w bf16 lo, same layout

#define SWZ128(off) ((off) ^ (((off) >> 3) & 0x70))

// ---------------- helpers ----------------
__device__ __forceinline__ uint32_t smem_u32(const void* p) {
    uint32_t a;
    asm("{ .reg .u64 t; cvta.to.shared.u64 t, %1; cvt.u32.u64 %0, t; }" : "=r"(a) : "l"(p));
    return a;
}
__device__ __forceinline__ void ldsm_x4(uint32_t* r, uint32_t addr) {
    asm volatile("ldmatrix.sync.aligned.m8n8.x4.shared.b16 {%0,%1,%2,%3}, [%4];"
        : "=r"(r[0]), "=r"(r[1]), "=r"(r[2]), "=r"(r[3]) : "r"(addr));
}
__device__ __forceinline__ void mma_bf16(float* d, const uint32_t* a, uint32_t b0, uint32_t b1) {
    asm volatile(
        "mma.sync.aligned.m16n8k16.row.col.f32.bf16.bf16.f32 "
        "{%0,%1,%2,%3}, {%4,%5,%6,%7}, {%8,%9}, {%0,%1,%2,%3};"
        : "+f"(d[0]), "+f"(d[1]), "+f"(d[2]), "+f"(d[3])
        : "r"(a[0]), "r"(a[1]), "r"(a[2]), "r"(a[3]), "r"(b0), "r"(b1));
}

// ---------------- prep: weight transforms ----------------
__global__ void prep_kernel(const float* __restrict__ off_w,
                            const float* __restrict__ def_w) {
    int idx = blockIdx.x * blockDim.x + threadIdx.x;
    const int n_w = GG*KK*CGc*CGc;    // 147456
    if (idx < n_w) {
        int ic = idx & 63;
        int oc = (idx >> 6) & 63;
        int gk = idx >> 12;           // g*9+k
        int k  = gk % KK;
        int g  = gk / KK;
        float w = def_w[((g*CGc + oc)*CGc + ic)*KK + k];
        __nv_bfloat16 hi = __float2bfloat16(w);
        float lo = w - __bfloat162float(hi);
        uint32_t sw = SWZ128((uint32_t)(oc*128 + ic*2));
        size_t base = (size_t)(g*KK + k) * CGc * CGc;
        g_wbh[base + sw/2] = hi;
        g_wbl[base + sw/2] = __float2bfloat16(lo);
    }
    const int n_owt = GG*CGc*KK*20;   // 46080
    if (idx < n_owt) {
        int c  = idx % 20;
        int t  = (idx / 20) % KK;
        int ic = (idx / 180) % CGc;
        int g  = idx / (180*CGc);
        g_owt[idx] = (c < 18) ? off_w[((g*18 + c)*CGc + ic)*KK + t] : 0.0f;
    }
}

// ---------------- offset conv: 64 -> 18, 3x3 (scalar fp32) ----------------
extern __shared__ float smem1[];
__global__ void __launch_bounds__(256) offset_kernel(const float* __restrict__ x,
                                                     const float* __restrict__ off_b) {
    float* sx = smem1;              // 3*64*64 floats
    float* sw = smem1 + 12288;      // 64*9*20 floats

    int bid = blockIdx.x;
    int h = bid & 63;
    int g = (bid >> 6) & 3;
    int b = bid >> 8;
    int tid = threadIdx.x;

    const float* owt = g_owt + g*CGc*KK*20;
    for (int i = tid; i < CGc*KK*20; i += 256) sw[i] = owt[i];

    const float* xb = x + (size_t)(b*GG + g) * CGc * HWs;
    for (int i = tid; i < 3*CGc*WW; i += 256) {
        int ky = i >> 12;
        int ic = (i >> 6) & 63;
        int w  = i & 63;
        int row = h - 1 + ky;
        sx[i] = (row >= 0 && row < HH) ? xb[ic*HWs + row*WW + w] : 0.0f;
    }
    __syncthreads();

    int w   = tid & 63;
    int sub = tid >> 6;

    float4 a4[5];
#pragma unroll
    for (int q = 0; q < 5; q++) a4[q] = make_float4(0.f,0.f,0.f,0.f);

#pragma unroll
    for (int ky = 0; ky < 3; ky++) {
        const float* sxk = sx + ky*4096;
        for (int ic = sub*16; ic < sub*16 + 16; ic++) {
            const float* xr = sxk + ic*64;
            float xv0 = (w > 0)  ? xr[w-1] : 0.0f;
            float xv1 = xr[w];
            float xv2 = (w < 63) ? xr[w+1] : 0.0f;
            const float4* wp = (const float4*)(sw + (ic*KK + ky*3)*20);
#pragma unroll
            for (int kx = 0; kx < 3; kx++) {
                float xs = (kx == 0) ? xv0 : ((kx == 1) ? xv1 : xv2);
#pragma unroll
                for (int q = 0; q < 5; q++) {
                    float4 wv = wp[kx*5 + q];
                    a4[q].x += wv.x * xs;
                    a4[q].y += wv.y * xs;
                    a4[q].z += wv.z * xs;
                    a4[q].w += wv.w * xs;
                }
            }
        }
    }
    __syncthreads();

    float* red = sx;
#pragma unroll
    for (int q = 0; q < 5; q++) {
        int c = q*4;
        if (c+0 < 18) red[(sub*18 + c+0)*64 + w] = a4[q].x;
        if (c+1 < 18) red[(sub*18 + c+1)*64 + w] = a4[q].y;
        if (c+2 < 18) red[(sub*18 + c+2)*64 + w] = a4[q].z;
        if (c+3 < 18) red[(sub*18 + c+3)*64 + w] = a4[q].w;
    }
    __syncthreads();

    for (int i = tid; i < 18*64; i += 256) {
        int c = i >> 6, ww = i & 63;
        float s = red[(0*18 + c)*64 + ww] + red[(1*18 + c)*64 + ww]
                + red[(2*18 + c)*64 + ww] + red[(3*18 + c)*64 + ww]
                + off_b[g*18 + c];
        g_off[((size_t)(b*GG + g)*18 + c)*HWs + h*64 + ww] = s;
    }
}

// ---------------- deformable conv: mma.sync bf16x2 GEMM ----------------
// block = (b, g, hblk of 2 rows); 128 threads (4 warps)
// M=128 (2h x 64w), N=64 oc, K per tap = 64 ic, 9 taps
#define SM_SHI  0        // S hi [128 x 64] bf16 SW128 : 16384 B
#define SM_SLO  16384    // S lo                       : 16384 B
#define SM_WHI  32768    // W hi [64 x 64] bf16 SW128  :  8192 B
#define SM_WLO  40960    // W lo                       :  8192 B
#define SM_TOTAL 49152

extern __shared__ char smem2[];
__global__ void __launch_bounds__(128) deform_kernel(const float* __restrict__ x,
                                                     const float* __restrict__ def_b,
                                                     float* __restrict__ out) {
    char* sm = smem2;
    uint32_t smem_base = smem_u32(sm);
    int tid  = threadIdx.x;
    int wid  = tid >> 5;
    int lane = tid & 31;

    int bid  = blockIdx.x;
    int hblk = bid & 31;
    int g    = (bid >> 5) & 3;
    int b    = bid >> 7;
    int bg   = b*GG + g;

    int m    = tid;            // S-tile row this thread gathers
    int r    = m >> 6;
    int wpos = m & 63;
    int h    = hblk*2 + r;

    const float* xb   = x + (size_t)bg * CGc * HWs;
    const float* offp = g_off + (size_t)bg * 18 * HWs + h*64 + wpos;

    char* shi_row = sm + SM_SHI + m*128;
    char* slo_row = sm + SM_SLO + m*128;
    uint32_t swz = (uint32_t)((m & 7) << 4);

    float acc[2][8][4];
#pragma unroll
    for (int mt = 0; mt < 2; mt++)
#pragma unroll
        for (int nt = 0; nt < 8; nt++)
#pragma unroll
            for (int q = 0; q < 4; q++) acc[mt][nt][q] = 0.0f;

    // per-thread ldmatrix row/col components
    int a_row0   = wid*32 + (lane & 15);        // + mt*16
    int ab_colsl = (lane >> 4) << 4;            // 0 or 16 bytes
    int b_row0   = ((lane >> 3) & 1)*8 + (lane & 7);  // + ntp*16

    for (int k = 0; k < KK; k++) {
        // ---- fill W tiles (pre-swizzled gmem -> linear copy) ----
        {
            const uint4* s1 = (const uint4*)(g_wbh + (size_t)(g*KK + k) * CGc * CGc);
            const uint4* s2 = (const uint4*)(g_wbl + (size_t)(g*KK + k) * CGc * CGc);
            uint4* d1 = (uint4*)(sm + SM_WHI);
            uint4* d2 = (uint4*)(sm + SM_WLO);
#pragma unroll
            for (int i = 0; i < 4; i++) {
                d1[tid + i*128] = s1[tid + i*128];
                d2[tid + i*128] = s2[tid + i*128];
            }
        }

        // ---- per-thread bilinear corner precompute ----
        float dy = __ldg(offp + (2*k    )*HWs);
        float dx = __ldg(offp + (2*k + 1)*HWs);
        float py = dy + (float)(k/3 - 1) + (float)h;
        float px = dx + (float)(k%3 - 1) + (float)wpos;
        float fy = floorf(py), fx = floorf(px);
        float wy = py - fy,    wx = px - fx;
        int y0 = (int)fy, x0 = (int)fx;
        int y1 = y0 + 1,  x1 = x0 + 1;
        float vy0 = (y0 >= 0 && y0 < HH) ? 1.f : 0.f;
        float vy1 = (y1 >= 0 && y1 < HH) ? 1.f : 0.f;
        float vx0 = (x0 >= 0 && x0 < WW) ? 1.f : 0.f;
        float vx1 = (x1 >= 0 && x1 < WW) ? 1.f : 0.f;
        float c00 = (1.f-wy)*(1.f-wx) * vy0 * vx0;
        float c01 = (1.f-wy)*wx       * vy0 * vx1;
        float c10 = wy*(1.f-wx)       * vy1 * vx0;
        float c11 = wy*wx             * vy1 * vx1;
        int y0c = min(max(y0,0),HH-1), y1c = min(max(y1,0),HH-1);
        int x0c = min(max(x0,0),WW-1), x1c = min(max(x1,0),WW-1);
        int o00 = y0c*WW + x0c, o01 = y0c*WW + x1c;
        int o10 = y1c*WW + x0c, o11 = y1c*WW + x1c;

        // ---- gather + bf16 hi/lo split into S tiles (thread owns row m) ----
#pragma unroll
        for (int icp = 0; icp < 8; icp++) {
            uint32_t hp[4], lp[4];
#pragma unroll
            for (int j = 0; j < 4; j++) {
                int ic = icp*8 + j*2;
                const float* p0 = xb + ic*HWs;
                const float* p1 = p0 + HWs;
                float v0 = c00*__ldg(p0+o00) + c01*__ldg(p0+o01)
                         + c10*__ldg(p0+o10) + c11*__ldg(p0+o11);
                float v1 = c00*__ldg(p1+o00) + c01*__ldg(p1+o01)
                         + c10*__ldg(p1+o10) + c11*__ldg(p1+o11);
                uint32_t hh;
                asm("cvt.rn.bf16x2.f32 %0, %1, %2;" : "=r"(hh) : "f"(v1), "f"(v0));
                float f0h = __uint_as_float(hh << 16);
                float f1h = __uint_as_float(hh & 0xffff0000u);
                float l0 = v0 - f0h, l1 = v1 - f1h;
                uint32_t ll;
                asm("cvt.rn.bf16x2.f32 %0, %1, %2;" : "=r"(ll) : "f"(l1), "f"(l0));
                hp[j] = hh; lp[j] = ll;
            }
            uint32_t off = ((uint32_t)(icp*16)) ^ swz;
            *(uint4*)(shi_row + off) = make_uint4(hp[0], hp[1], hp[2], hp[3]);
            *(uint4*)(slo_row + off) = make_uint4(lp[0], lp[1], lp[2], lp[3]);
        }
        __syncthreads();

        // ---- MMA: 4 k16-chunks x (2 m-tiles x 8 n-tiles) x 3 bf16x2 terms ----
#pragma unroll
        for (int kc = 0; kc < 4; kc++) {
            int colb = kc*32 + ab_colsl;
            uint32_t ah[2][4], al[2][4];
#pragma unroll
            for (int mt = 0; mt < 2; mt++) {
                int row = a_row0 + mt*16;
                uint32_t boff = (uint32_t)(row*128 + (colb ^ ((row & 7) << 4)));
                ldsm_x4(ah[mt], smem_base + SM_SHI + boff);
                ldsm_x4(al[mt], smem_base + SM_SLO + boff);
            }
#pragma unroll
            for (int ntp = 0; ntp < 4; ntp++) {
                int nrow = b_row0 + ntp*16;
                uint32_t boff = (uint32_t)(nrow*128 + (colb ^ ((nrow & 7) << 4)));
                uint32_t bh[4], bl[4];
                ldsm_x4(bh, smem_base + SM_WHI + boff);
                ldsm_x4(bl, smem_base + SM_WLO + boff);
#pragma unroll
                for (int mt = 0; mt < 2; mt++) {
                    // n-tile 2*ntp: frags {r0, r2}; n-tile 2*ntp+1: {r1, r3}
                    mma_bf16(acc[mt][2*ntp  ], ah[mt], bh[0], bh[2]);
                    mma_bf16(acc[mt][2*ntp  ], ah[mt], bl[0], bl[2]);
                    mma_bf16(acc[mt][2*ntp  ], al[mt], bh[0], bh[2]);
                    mma_bf16(acc[mt][2*ntp+1], ah[mt], bh[1], bh[3]);
                    mma_bf16(acc[mt][2*ntp+1], ah[mt], bl[1], bl[3]);
                    mma_bf16(acc[mt][2*ntp+1], al[mt], bh[1], bh[3]);
                }
            }
        }
        __syncthreads();   // all warps done reading S/W before next tap overwrites
    }

    // ---- epilogue: fragment scatter to gmem (+bias) ----
    float* outg = out + (size_t)bg * CGc * HWs + hblk*2*64;
    const float* bbp = def_b + g*CGc;
#pragma unroll
    for (int mt = 0; mt < 2; mt++) {
        int row0  = wid*32 + mt*16 + (lane >> 2);
        int h_loc = row0 >> 6;
        int wp    = row0 & 63;
        float* p0 = outg + h_loc*64 + wp;
        float* p1 = p0 + 8;   // row0+8 stays in same 64-row band
#pragma unroll
        for (int nt = 0; nt < 8; nt++) {
            int oc0 = nt*8 + (lane & 3)*2;
            float bz0 = __ldg(bbp + oc0);
            float bz1 = __ldg(bbp + oc0 + 1);
            p0[(size_t)oc0*HWs]       = acc[mt][nt][0] + bz0;
            p0[(size_t)(oc0+1)*HWs]   = acc[mt][nt][1] + bz1;
            p1[(size_t)oc0*HWs]       = acc[mt][nt][2] + bz0;
            p1[(size_t)(oc0+1)*HWs]   = acc[mt][nt][3] + bz1;
        }
    }
}

// ---------------- launch ----------------
extern "C" void kernel_launch(void* const* d_in, const int* in_sizes, int n_in,
                              void* d_out, int out_size) {
    const float* x     = (const float*)d_in[0];
    const float* off_w = (const float*)d_in[1];
    const float* off_b = (const float*)d_in[2];
    const float* def_w = (const float*)d_in[3];
    const float* def_b = (const float*)d_in[4];
    float* out = (float*)d_out;

    cudaFuncSetAttribute(offset_kernel, cudaFuncAttributeMaxDynamicSharedMemorySize,
                         (12288 + 11520) * (int)sizeof(float));   // 95232 B
    cudaFuncSetAttribute(deform_kernel, cudaFuncAttributeMaxDynamicSharedMemorySize,
                         SM_TOTAL);                               // 49152 B

    prep_kernel<<<(GG*KK*CGc*CGc + 255) / 256, 256>>>(off_w, def_w);
    offset_kernel<<<BB*GG*HH, 256, (12288 + 11520) * sizeof(float)>>>(x, off_b);
    deform_kernel<<<BB*GG*(HH/2), 128, SM_TOTAL>>>(x, def_b, out);
}